// round 11
// baseline (speedup 1.0000x reference)
#include <cuda_runtime.h>
#include <math.h>

#define N_BATCH 32
#define C_IN    256
#define C_SQ    64
#define HW      12544              // 112*112
#define HW4     3136               // float4 per plane = 448*7
#define PLANES  (N_BATCH * C_IN)   // 8192
#define TPB     448
#define VPT     7
#define NBLK    296                // 2 blocks/SM x 148 SMs (<= resident on 152-SM GB300 too)

// Scratch (no allocations allowed). Zero-initialized by CUDA runtime.
__device__ float    g_pool[PLANES];
__device__ float    g_gate[PLANES];
__device__ unsigned g_bar_count;
__device__ unsigned g_bar_gen;

__device__ __forceinline__ unsigned ld_acquire_gpu(const unsigned* p) {
    unsigned v;
    asm volatile("ld.acquire.gpu.u32 %0, [%1];" : "=r"(v) : "l"(p) : "memory");
    return v;
}

// Sense-reversing grid barrier. Safe because the grid (296 blocks) is fully
// resident. Self-resetting (count -> 0 by last arriver; gen monotonic), so it
// works across CUDA-graph replays.
__device__ __forceinline__ void grid_barrier() {
    __syncthreads();
    if (threadIdx.x == 0) {
        __threadfence();                                   // release my writes
        unsigned gen = ld_acquire_gpu(&g_bar_gen);
        unsigned old = atomicAdd(&g_bar_count, 1u);
        if (old == NBLK - 1u) {
            g_bar_count = 0u;
            __threadfence();                               // order reset before publish
            atomicAdd(&g_bar_gen, 1u);
        } else {
            while (ld_acquire_gpu(&g_bar_gen) == gen)
                __nanosleep(32);
        }
    }
    __syncthreads();
}

// ---------------------------------------------------------------------------
// Persistent fused kernel: pool -> barrier -> MLP -> barrier -> scale.
// No kernel boundaries, no HBM re-ramp between phases.
// ---------------------------------------------------------------------------
__global__ __launch_bounds__(TPB, 2) void se_persistent_kernel(
    const float* __restrict__ x,
    float*       __restrict__ out,
    const float* __restrict__ w_reduce,   // [C_SQ, C_IN]
    const float* __restrict__ b_reduce,   // [C_SQ]
    const float* __restrict__ w_expand,   // [C_IN, C_SQ]
    const float* __restrict__ b_expand)   // [C_IN]
{
    const int tid  = threadIdx.x;
    const int lane = tid & 31;
    const int wid  = tid >> 5;

    __shared__ float warp_sums[TPB / 32];  // 14

    // ---------------- Phase 1: pool (grid-stride over planes) ----------------
    for (int plane = blockIdx.x; plane < PLANES; plane += NBLK) {
        const float4* p = reinterpret_cast<const float4*>(x + (size_t)plane * HW);

        float4 v0 = p[tid + 0 * TPB];
        float4 v1 = p[tid + 1 * TPB];
        float4 v2 = p[tid + 2 * TPB];
        float4 v3 = p[tid + 3 * TPB];
        float4 v4 = p[tid + 4 * TPB];
        float4 v5 = p[tid + 5 * TPB];
        float4 v6 = p[tid + 6 * TPB];

        float sum = ((v0.x + v0.y) + (v0.z + v0.w))
                  + ((v1.x + v1.y) + (v1.z + v1.w))
                  + ((v2.x + v2.y) + (v2.z + v2.w))
                  + ((v3.x + v3.y) + (v3.z + v3.w))
                  + ((v4.x + v4.y) + (v4.z + v4.w))
                  + ((v5.x + v5.y) + (v5.z + v5.w))
                  + ((v6.x + v6.y) + (v6.z + v6.w));

        #pragma unroll
        for (int off = 16; off > 0; off >>= 1)
            sum += __shfl_down_sync(0xFFFFFFFFu, sum, off);

        if (lane == 0) warp_sums[wid] = sum;
        __syncthreads();
        if (tid == 0) {
            float s = 0.0f;
            #pragma unroll
            for (int w = 0; w < TPB / 32; w++) s += warp_sums[w];
            g_pool[plane] = s * (1.0f / (float)HW);
        }
        __syncthreads();
    }

    grid_barrier();

    // ---------------- Phase 2: MLP (blocks 0..31, one batch each) ------------
    if (blockIdx.x < N_BATCH) {
        const int n = blockIdx.x;
        __shared__ float s_in[C_IN];
        __shared__ float s_red[C_SQ];

        if (tid < C_IN) s_in[tid] = __ldcg(&g_pool[n * C_IN + tid]);
        __syncthreads();

        if (tid < C_SQ) {
            float a0 = b_reduce[tid], a1 = 0.f, a2 = 0.f, a3 = 0.f;
            const float* wr = w_reduce + tid * C_IN;
            #pragma unroll 4
            for (int k = 0; k < C_IN; k += 4) {
                a0 = fmaf(wr[k + 0], s_in[k + 0], a0);
                a1 = fmaf(wr[k + 1], s_in[k + 1], a1);
                a2 = fmaf(wr[k + 2], s_in[k + 2], a2);
                a3 = fmaf(wr[k + 3], s_in[k + 3], a3);
            }
            s_red[tid] = fmaxf((a0 + a1) + (a2 + a3), 0.0f);
        }
        __syncthreads();

        if (tid < C_IN) {
            float acc = b_expand[tid];
            const float* we = w_expand + tid * C_SQ;
            #pragma unroll 8
            for (int k = 0; k < C_SQ; k++)
                acc = fmaf(we[k], s_red[k], acc);
            g_gate[n * C_IN + tid] = 1.0f / (1.0f + __expf(-acc));
        }
    }

    grid_barrier();

    // ---------------- Phase 3: scale (reverse order for L2 tail hits) --------
    for (int idx = blockIdx.x; idx < PLANES; idx += NBLK) {
        const int plane = (PLANES - 1) - idx;
        const float g = __ldcg(&g_gate[plane]);

        const float4* p = reinterpret_cast<const float4*>(x   + (size_t)plane * HW);
        float4*       q = reinterpret_cast<float4*>(out       + (size_t)plane * HW);

        float4 v[VPT];
        #pragma unroll
        for (int i = 0; i < VPT; i++)
            v[i] = p[tid + i * TPB];

        #pragma unroll
        for (int i = 0; i < VPT; i++) {
            v[i].x *= g; v[i].y *= g; v[i].z *= g; v[i].w *= g;
            __stcs(&q[tid + i * TPB], v[i]);
        }
    }
}

// ---------------------------------------------------------------------------
extern "C" void kernel_launch(void* const* d_in, const int* in_sizes, int n_in,
                              void* d_out, int out_size)
{
    const float* x        = (const float*)d_in[0];
    const float* w_reduce = (const float*)d_in[1];
    const float* b_reduce = (const float*)d_in[2];
    const float* w_expand = (const float*)d_in[3];
    const float* b_expand = (const float*)d_in[4];
    float* out = (float*)d_out;

    se_persistent_kernel<<<NBLK, TPB>>>(x, out, w_reduce, b_reduce,
                                        w_expand, b_expand);
}